// round 1
// baseline (speedup 1.0000x reference)
#include <cuda_runtime.h>
#include <cuda_bf16.h>
#include <math.h>

// Problem constants
#define B_SZ     4096
#define K_EMB    64
#define N_FEAT   8
#define L_ITEM   350
#define L_AUTHOR 250
#define L_MUSIC  100
#define D_IN     704     // 3*64 + 8*64
#define H1       512
#define H2       256
#define H3       128
#define PAD_IDX  1000000

// Scratch (device globals — allocation-free)
__device__ float g_x [B_SZ * D_IN];   // [B, 704] MLP input
__device__ float g_h1[B_SZ * H1];
__device__ float g_h2[B_SZ * H2];
__device__ float g_h3[B_SZ * H3];

// ---------------------------------------------------------------------------
// Attention pool: one block (128 thr = 4 warps) per batch row.
// Online softmax per warp; each lane owns 2 of the 64 embedding components.
// Reads each gathered embedding exactly once.
// ---------------------------------------------------------------------------
__global__ __launch_bounds__(128) void attn_pool_kernel(
    const int* __restrict__ feat,     // [B, 8]
    const int* __restrict__ hist,     // [B, L]
    const float* __restrict__ table,  // [V, 64]
    float* __restrict__ xout,         // [B, 704]
    int L, int ad_col, int pool_off)
{
    const int row  = blockIdx.x;
    const int lane = threadIdx.x & 31;
    const int warp = threadIdx.x >> 5;

    __shared__ float s_ad[K_EMB];
    __shared__ float s_m[4], s_s[4];
    __shared__ float s_acc[4][K_EMB];

    // Load ad embedding (always a valid index: ad cols drawn in [0, PAD_IDX))
    const int ad_idx = feat[row * N_FEAT + ad_col];
    if (threadIdx.x < K_EMB)
        s_ad[threadIdx.x] = table[(size_t)ad_idx * K_EMB + threadIdx.x];
    __syncthreads();

    const float2 ad2 = *(const float2*)&s_ad[lane * 2];

    float m = -INFINITY, s = 0.f;
    float2 acc = make_float2(0.f, 0.f);

    for (int l = warp; l < L; l += 4) {
        const int idx = hist[row * L + l];      // uniform across warp
        if (idx == PAD_IDX) continue;           // exp(-1e9 - m) == 0 in fp32
        const float2 e = *(const float2*)&table[(size_t)idx * K_EMB + lane * 2];
        float d = e.x * ad2.x + e.y * ad2.y;
        #pragma unroll
        for (int o = 16; o; o >>= 1) d += __shfl_xor_sync(0xffffffffu, d, o);

        const float nm    = fmaxf(m, d);
        const float scale = __expf(m - nm);     // m=-inf -> 0, safe
        const float p     = __expf(d - nm);
        s     = s * scale + p;
        acc.x = acc.x * scale + p * e.x;
        acc.y = acc.y * scale + p * e.y;
        m = nm;
    }

    if (lane == 0) { s_m[warp] = m; s_s[warp] = s; }
    s_acc[warp][lane * 2]     = acc.x;
    s_acc[warp][lane * 2 + 1] = acc.y;
    __syncthreads();

    if (threadIdx.x < K_EMB) {
        float M = fmaxf(fmaxf(s_m[0], s_m[1]), fmaxf(s_m[2], s_m[3]));
        float S = 0.f, num = 0.f;
        #pragma unroll
        for (int w = 0; w < 4; w++) {
            const float sc = __expf(s_m[w] - M);   // m=-inf warp -> 0 contribution
            S   += s_s[w] * sc;
            num += s_acc[w][threadIdx.x] * sc;
        }
        xout[(size_t)row * D_IN + pool_off + threadIdx.x] = num / S;
    }
}

// ---------------------------------------------------------------------------
// Ad-embedding gather: one block per row, 128 threads copy 8*64 floats (float4)
// ---------------------------------------------------------------------------
__global__ __launch_bounds__(128) void ad_gather_kernel(
    const int* __restrict__ feat,
    const float* __restrict__ table,
    float* __restrict__ xout)
{
    const int row = blockIdx.x;
    const int t   = threadIdx.x;
    const int f   = t >> 4;          // feature 0..7
    const int c   = t & 15;          // float4 slot 0..15
    const int idx = feat[row * N_FEAT + f];
    const float4 v = *(const float4*)&table[(size_t)idx * K_EMB + c * 4];
    *(float4*)&xout[(size_t)row * D_IN + 3 * K_EMB + f * K_EMB + c * 4] = v;
}

// ---------------------------------------------------------------------------
// SGEMM + bias + optional ReLU.  C[M,N] = act(A[M,K] @ W[K,N] + bias)
// 64x64 block tile, BK=16, 256 threads, 4x4 microtile, float4 smem reads.
// All dims here are multiples of the tiles (no bounds checks needed).
// ---------------------------------------------------------------------------
#define BM 64
#define BN 64
#define BK 16

__global__ __launch_bounds__(256) void gemm_bias_act(
    const float* __restrict__ A, const float* __restrict__ W,
    const float* __restrict__ bias, float* __restrict__ C,
    int M, int N, int K, int relu)
{
    __shared__ float As[BK][BM];
    __shared__ float Bs[BK][BN];

    const int tid = threadIdx.x;
    const int tx  = tid & 15;   // col group (x4)
    const int ty  = tid >> 4;   // row group (x4)
    const int bm  = blockIdx.y * BM;
    const int bn  = blockIdx.x * BN;

    const int arow = tid >> 2, acol = (tid & 3) * 4;    // A tile: 64x16
    const int brow = tid >> 4, bcol = (tid & 15) * 4;   // W tile: 16x64

    float acc[4][4] = {};

    for (int k0 = 0; k0 < K; k0 += BK) {
        const float4 a = *(const float4*)&A[(size_t)(bm + arow) * K + k0 + acol];
        As[acol + 0][arow] = a.x;
        As[acol + 1][arow] = a.y;
        As[acol + 2][arow] = a.z;
        As[acol + 3][arow] = a.w;
        const float4 b = *(const float4*)&W[(size_t)(k0 + brow) * N + bn + bcol];
        *(float4*)&Bs[brow][bcol] = b;
        __syncthreads();

        #pragma unroll
        for (int k = 0; k < BK; k++) {
            const float4 ra = *(const float4*)&As[k][ty * 4];
            const float4 rb = *(const float4*)&Bs[k][tx * 4];
            const float rav[4] = {ra.x, ra.y, ra.z, ra.w};
            const float rbv[4] = {rb.x, rb.y, rb.z, rb.w};
            #pragma unroll
            for (int i = 0; i < 4; i++)
                #pragma unroll
                for (int j = 0; j < 4; j++)
                    acc[i][j] += rav[i] * rbv[j];
        }
        __syncthreads();
    }

    #pragma unroll
    for (int i = 0; i < 4; i++) {
        const int r = bm + ty * 4 + i;
        #pragma unroll
        for (int j = 0; j < 4; j++) {
            const int c = bn + tx * 4 + j;
            float v = acc[i][j] + bias[c];
            if (relu) v = fmaxf(v, 0.f);
            C[(size_t)r * N + c] = v;
        }
    }
}

// ---------------------------------------------------------------------------
// Final: logits[row] = h3[row, :128] . Wo + bo.  One warp per row.
// ---------------------------------------------------------------------------
__global__ __launch_bounds__(128) void final_dot_kernel(
    const float* __restrict__ h3, const float* __restrict__ Wo,
    const float* __restrict__ bo, float* __restrict__ out)
{
    const int lane = threadIdx.x & 31;
    const int warp = threadIdx.x >> 5;
    const int row  = blockIdx.x * 4 + warp;
    float sum = 0.f;
    #pragma unroll
    for (int i = lane; i < H3; i += 32)
        sum += h3[(size_t)row * H3 + i] * Wo[i];
    #pragma unroll
    for (int o = 16; o; o >>= 1) sum += __shfl_xor_sync(0xffffffffu, sum, o);
    if (lane == 0) out[row] = sum + bo[0];
}

// ---------------------------------------------------------------------------
extern "C" void kernel_launch(void* const* d_in, const int* in_sizes, int n_in,
                              void* d_out, int out_size)
{
    const int*   feat   = (const int*)  d_in[0];
    const int*   h_item = (const int*)  d_in[1];
    const int*   h_auth = (const int*)  d_in[2];
    const int*   h_mus  = (const int*)  d_in[3];
    const float* table  = (const float*)d_in[4];
    const float* W1 = (const float*)d_in[5];
    const float* b1 = (const float*)d_in[6];
    const float* W2 = (const float*)d_in[7];
    const float* b2 = (const float*)d_in[8];
    const float* W3 = (const float*)d_in[9];
    const float* b3 = (const float*)d_in[10];
    const float* Wo = (const float*)d_in[11];
    const float* bo = (const float*)d_in[12];
    float* out = (float*)d_out;

    float* x  = nullptr; cudaGetSymbolAddress((void**)&x,  g_x);
    float* h1 = nullptr; cudaGetSymbolAddress((void**)&h1, g_h1);
    float* h2 = nullptr; cudaGetSymbolAddress((void**)&h2, g_h2);
    float* h3 = nullptr; cudaGetSymbolAddress((void**)&h3, g_h3);

    // Attention pools (ad columns 2, 3, 6 -> x cols [0,64), [64,128), [128,192))
    attn_pool_kernel<<<B_SZ, 128>>>(feat, h_item, table, x, L_ITEM,   2, 0);
    attn_pool_kernel<<<B_SZ, 128>>>(feat, h_auth, table, x, L_AUTHOR, 3, K_EMB);
    attn_pool_kernel<<<B_SZ, 128>>>(feat, h_mus,  table, x, L_MUSIC,  6, 2 * K_EMB);

    // Ad embedding gather -> x cols [192, 704)
    ad_gather_kernel<<<B_SZ, 128>>>(feat, table, x);

    // MLP
    {
        dim3 g1(H1 / BN, B_SZ / BM);
        gemm_bias_act<<<g1, 256>>>(x,  W1, b1, h1, B_SZ, H1, D_IN, 1);
        dim3 g2(H2 / BN, B_SZ / BM);
        gemm_bias_act<<<g2, 256>>>(h1, W2, b2, h2, B_SZ, H2, H1, 1);
        dim3 g3(H3 / BN, B_SZ / BM);
        gemm_bias_act<<<g3, 256>>>(h2, W3, b3, h3, B_SZ, H3, H2, 1);
    }

    final_dot_kernel<<<B_SZ / 4, 128>>>(h3, Wo, bo, out);
}

// round 10
// speedup vs baseline: 1.2068x; 1.2068x over previous
#include <cuda_runtime.h>
#include <cuda_bf16.h>
#include <mma.h>
#include <math.h>
#include <stdint.h>

using namespace nvcuda;

#define B_SZ     4096
#define K_EMB    64
#define N_FEAT   8
#define L_ITEM   350
#define L_AUTHOR 250
#define L_MUSIC  100
#define D_IN     704     // 3*64 + 8*64
#define H1       512
#define H2       256
#define H3       128
#define PAD_IDX  1000000

// Scratch (device globals — allocation-free)
__device__ float g_x [B_SZ * D_IN];
__device__ float g_h1[B_SZ * H1];
__device__ float g_h2[B_SZ * H2];
__device__ float g_h3[B_SZ * H3];

// ---------------------------------------------------------------------------
// Attention pool (UNCHANGED from the 403us passing kernel).
// One block (128 thr = 4 warps) per batch row; online softmax per warp.
// ---------------------------------------------------------------------------
__global__ __launch_bounds__(128) void attn_pool_kernel(
    const int* __restrict__ feat,
    const int* __restrict__ hist,
    const float* __restrict__ table,
    float* __restrict__ xout,
    int L, int ad_col, int pool_off)
{
    const int row  = blockIdx.x;
    const int lane = threadIdx.x & 31;
    const int warp = threadIdx.x >> 5;

    __shared__ float s_ad[K_EMB];
    __shared__ float s_m[4], s_s[4];
    __shared__ float s_acc[4][K_EMB];

    const int ad_idx = feat[row * N_FEAT + ad_col];
    if (threadIdx.x < K_EMB)
        s_ad[threadIdx.x] = table[(size_t)ad_idx * K_EMB + threadIdx.x];
    __syncthreads();

    const float2 ad2 = *(const float2*)&s_ad[lane * 2];

    float m = -INFINITY, s = 0.f;
    float2 acc = make_float2(0.f, 0.f);

    for (int l = warp; l < L; l += 4) {
        const int idx = hist[row * L + l];
        if (idx == PAD_IDX) continue;
        const float2 e = *(const float2*)&table[(size_t)idx * K_EMB + lane * 2];
        float d = e.x * ad2.x + e.y * ad2.y;
        #pragma unroll
        for (int o = 16; o; o >>= 1) d += __shfl_xor_sync(0xffffffffu, d, o);

        const float nm    = fmaxf(m, d);
        const float scale = __expf(m - nm);
        const float p     = __expf(d - nm);
        s     = s * scale + p;
        acc.x = acc.x * scale + p * e.x;
        acc.y = acc.y * scale + p * e.y;
        m = nm;
    }

    if (lane == 0) { s_m[warp] = m; s_s[warp] = s; }
    s_acc[warp][lane * 2]     = acc.x;
    s_acc[warp][lane * 2 + 1] = acc.y;
    __syncthreads();

    if (threadIdx.x < K_EMB) {
        float M = fmaxf(fmaxf(s_m[0], s_m[1]), fmaxf(s_m[2], s_m[3]));
        float S = 0.f, num = 0.f;
        #pragma unroll
        for (int w = 0; w < 4; w++) {
            const float sc = __expf(s_m[w] - M);
            S   += s_s[w] * sc;
            num += s_acc[w][threadIdx.x] * sc;
        }
        xout[(size_t)row * D_IN + pool_off + threadIdx.x] = num / S;
    }
}

// ---------------------------------------------------------------------------
// Ad-embedding gather (UNCHANGED).
// ---------------------------------------------------------------------------
__global__ __launch_bounds__(128) void ad_gather_kernel(
    const int* __restrict__ feat,
    const float* __restrict__ table,
    float* __restrict__ xout)
{
    const int row = blockIdx.x;
    const int t   = threadIdx.x;
    const int f   = t >> 4;
    const int c   = t & 15;
    const int idx = feat[row * N_FEAT + f];
    const float4 v = *(const float4*)&table[(size_t)idx * K_EMB + c * 4];
    *(float4*)&xout[(size_t)row * D_IN + 3 * K_EMB + f * K_EMB + c * 4] = v;
}

// ---------------------------------------------------------------------------
// Tensor-core GEMM + bias + ReLU via WMMA bf16 (bf16x3 split, fp32 accum).
// C[M,N] = act(A[M,K] @ W[K,N] + bias).
// Block tile 128x64, BK=32, 256 threads = 8 warps (4m x 2n), 32x32 per warp.
// M,N,K are all multiples of the tiles here -> no bounds checks.
// ---------------------------------------------------------------------------
#define BM   128
#define BN   64
#define BK   32
#define APAD 8     // Ah/Al row stride 40 bf16 = 80 B  (16B-aligned rows)
#define BPAD 8     // Bh/Bl row stride 72 bf16 = 144 B (16B-aligned rows)

__global__ __launch_bounds__(256) void gemm_bias_act(
    const float* __restrict__ A, const float* __restrict__ W,
    const float* __restrict__ bias, float* __restrict__ C,
    int M, int N, int K, int relu)
{
    __shared__ __nv_bfloat16 Ah[BM][BK + APAD];
    __shared__ __nv_bfloat16 Al[BM][BK + APAD];
    __shared__ __nv_bfloat16 Bh[BK][BN + BPAD];
    __shared__ __nv_bfloat16 Bl[BK][BN + BPAD];
    __shared__ float bias_s[16][BN + 4];   // 16 replicated rows of bias

    const int tid  = threadIdx.x;
    const int warp = tid >> 5;
    const int wm   = warp & 3;    // warp m index: 0..3 (x32 rows)
    const int wn   = warp >> 2;   // warp n index: 0..1 (x32 cols)
    const int bm   = blockIdx.y * BM;
    const int bn   = blockIdx.x * BN;

    // Build replicated bias tile
    for (int i = tid; i < 16 * BN; i += 256) {
        const int r = i >> 6, c = i & 63;
        bias_s[r][c] = bias[bn + c];
    }
    __syncthreads();

    // Accumulators pre-loaded with bias
    wmma::fragment<wmma::accumulator, 16, 16, 16, float> acc[2][2];
    #pragma unroll
    for (int mi = 0; mi < 2; mi++)
        #pragma unroll
        for (int ni = 0; ni < 2; ni++)
            wmma::load_matrix_sync(acc[mi][ni], &bias_s[0][wn * 32 + ni * 16],
                                   BN + 4, wmma::mem_row_major);

    // gmem->smem mapping: A tile 128x32 (16 floats/thr), W tile 32x64 (8/thr)
    const int arow = tid >> 1, ac0 = (tid & 1) * 16;
    const int brow = tid >> 3, bc0 = (tid & 7) * 8;

    for (int k0 = 0; k0 < K; k0 += BK) {
        #pragma unroll
        for (int i = 0; i < 4; i++) {
            const float4 v = *(const float4*)&A[(size_t)(bm + arow) * K + k0 + ac0 + i * 4];
            const float f[4] = {v.x, v.y, v.z, v.w};
            __nv_bfloat16 hi[4], lo[4];
            #pragma unroll
            for (int j = 0; j < 4; j++) {
                hi[j] = __float2bfloat16(f[j]);
                lo[j] = __float2bfloat16(f[j] - __bfloat162float(hi[j]));
            }
            *(uint2*)&Ah[arow][ac0 + i * 4] = *(uint2*)hi;
            *(uint2*)&Al[arow][ac0 + i * 4] = *(uint2*)lo;
        }
        #pragma unroll
        for (int i = 0; i < 2; i++) {
            const float4 v = *(const float4*)&W[(size_t)(k0 + brow) * N + bn + bc0 + i * 4];
            const float f[4] = {v.x, v.y, v.z, v.w};
            __nv_bfloat16 hi[4], lo[4];
            #pragma unroll
            for (int j = 0; j < 4; j++) {
                hi[j] = __float2bfloat16(f[j]);
                lo[j] = __float2bfloat16(f[j] - __bfloat162float(hi[j]));
            }
            *(uint2*)&Bh[brow][bc0 + i * 4] = *(uint2*)hi;
            *(uint2*)&Bl[brow][bc0 + i * 4] = *(uint2*)lo;
        }
        __syncthreads();

        #pragma unroll
        for (int kk = 0; kk < BK; kk += 16) {
            wmma::fragment<wmma::matrix_a, 16, 16, 16, __nv_bfloat16, wmma::row_major> a_h[2], a_l[2];
            wmma::fragment<wmma::matrix_b, 16, 16, 16, __nv_bfloat16, wmma::row_major> b_h[2], b_l[2];
            #pragma unroll
            for (int mi = 0; mi < 2; mi++) {
                wmma::load_matrix_sync(a_h[mi], &Ah[wm * 32 + mi * 16][kk], BK + APAD);
                wmma::load_matrix_sync(a_l[mi], &Al[wm * 32 + mi * 16][kk], BK + APAD);
            }
            #pragma unroll
            for (int ni = 0; ni < 2; ni++) {
                wmma::load_matrix_sync(b_h[ni], &Bh[kk][wn * 32 + ni * 16], BN + BPAD);
                wmma::load_matrix_sync(b_l[ni], &Bl[kk][wn * 32 + ni * 16], BN + BPAD);
            }
            #pragma unroll
            for (int mi = 0; mi < 2; mi++)
                #pragma unroll
                for (int ni = 0; ni < 2; ni++) {
                    wmma::mma_sync(acc[mi][ni], a_h[mi], b_h[ni], acc[mi][ni]); // hi*hi
                    wmma::mma_sync(acc[mi][ni], a_h[mi], b_l[ni], acc[mi][ni]); // hi*lo
                    wmma::mma_sync(acc[mi][ni], a_l[mi], b_h[ni], acc[mi][ni]); // lo*hi
                }
        }
        __syncthreads();
    }

    // ReLU (elementwise on fragment) + store
    #pragma unroll
    for (int mi = 0; mi < 2; mi++)
        #pragma unroll
        for (int ni = 0; ni < 2; ni++) {
            if (relu) {
                #pragma unroll
                for (int e = 0; e < acc[mi][ni].num_elements; e++)
                    acc[mi][ni].x[e] = fmaxf(acc[mi][ni].x[e], 0.f);
            }
            wmma::store_matrix_sync(
                &C[(size_t)(bm + wm * 32 + mi * 16) * N + bn + wn * 32 + ni * 16],
                acc[mi][ni], N, wmma::mem_row_major);
        }
}

// ---------------------------------------------------------------------------
// Final: logits[row] = h3[row,:128] . Wo + bo. One warp per row (UNCHANGED).
// ---------------------------------------------------------------------------
__global__ __launch_bounds__(128) void final_dot_kernel(
    const float* __restrict__ h3, const float* __restrict__ Wo,
    const float* __restrict__ bo, float* __restrict__ out)
{
    const int lane = threadIdx.x & 31;
    const int warp = threadIdx.x >> 5;
    const int row  = blockIdx.x * 4 + warp;
    float sum = 0.f;
    #pragma unroll
    for (int i = lane; i < H3; i += 32)
        sum += h3[(size_t)row * H3 + i] * Wo[i];
    #pragma unroll
    for (int o = 16; o; o >>= 1) sum += __shfl_xor_sync(0xffffffffu, sum, o);
    if (lane == 0) out[row] = sum + bo[0];
}

// ---------------------------------------------------------------------------
extern "C" void kernel_launch(void* const* d_in, const int* in_sizes, int n_in,
                              void* d_out, int out_size)
{
    const int*   feat   = (const int*)  d_in[0];
    const int*   h_item = (const int*)  d_in[1];
    const int*   h_auth = (const int*)  d_in[2];
    const int*   h_mus  = (const int*)  d_in[3];
    const float* table  = (const float*)d_in[4];
    const float* W1 = (const float*)d_in[5];
    const float* b1 = (const float*)d_in[6];
    const float* W2 = (const float*)d_in[7];
    const float* b2 = (const float*)d_in[8];
    const float* W3 = (const float*)d_in[9];
    const float* b3 = (const float*)d_in[10];
    const float* Wo = (const float*)d_in[11];
    const float* bo = (const float*)d_in[12];
    float* out = (float*)d_out;

    float* x  = nullptr; cudaGetSymbolAddress((void**)&x,  g_x);
    float* h1 = nullptr; cudaGetSymbolAddress((void**)&h1, g_h1);
    float* h2 = nullptr; cudaGetSymbolAddress((void**)&h2, g_h2);
    float* h3 = nullptr; cudaGetSymbolAddress((void**)&h3, g_h3);

    // Pools + ad gather (known-good kernels)
    attn_pool_kernel<<<B_SZ, 128>>>(feat, h_item, table, x, L_ITEM,   2, 0);
    attn_pool_kernel<<<B_SZ, 128>>>(feat, h_auth, table, x, L_AUTHOR, 3, K_EMB);
    attn_pool_kernel<<<B_SZ, 128>>>(feat, h_mus,  table, x, L_MUSIC,  6, 2 * K_EMB);
    ad_gather_kernel<<<B_SZ, 128>>>(feat, table, x);

    // MLP on tensor cores (bf16x3)
    gemm_bias_act<<<dim3(H1 / BN, B_SZ / BM), 256>>>(x,  W1, b1, h1, B_SZ, H1, D_IN, 1);
    gemm_bias_act<<<dim3(H2 / BN, B_SZ / BM), 256>>>(h1, W2, b2, h2, B_SZ, H2, H1, 1);
    gemm_bias_act<<<dim3(H3 / BN, B_SZ / BM), 256>>>(h2, W3, b3, h3, B_SZ, H3, H2, 1);

    final_dot_kernel<<<B_SZ / 4, 128>>>(h3, Wo, bo, out);
}

// round 17
// speedup vs baseline: 1.6521x; 1.3690x over previous
#include <cuda_runtime.h>
#include <cuda_bf16.h>
#include <mma.h>
#include <math.h>
#include <stdint.h>

using namespace nvcuda;

#define B_SZ     4096
#define K_EMB    64
#define N_FEAT   8
#define D_IN     704     // 3*64 + 8*64
#define H1       512
#define H2       256
#define H3       128
#define PAD_IDX  1000000

// Scratch (device globals — allocation-free)
__device__ float g_x [B_SZ * D_IN];
__device__ float g_h1[B_SZ * H1];
__device__ float g_h2[B_SZ * H2];
__device__ float g_h3[B_SZ * H3];

// Pre-split bf16 weights (hi/lo)
__device__ __nv_bfloat16 g_w1h[D_IN * H1], g_w1l[D_IN * H1];
__device__ __nv_bfloat16 g_w2h[H1 * H2],   g_w2l[H1 * H2];
__device__ __nv_bfloat16 g_w3h[H2 * H3],   g_w3l[H2 * H3];

// ---------------------------------------------------------------------------
// Split a float array into bf16 hi + lo.
// ---------------------------------------------------------------------------
__global__ void split_kernel(const float* __restrict__ src,
                             __nv_bfloat16* __restrict__ hi,
                             __nv_bfloat16* __restrict__ lo, int n)
{
    const int i = blockIdx.x * blockDim.x + threadIdx.x;
    if (i >= n) return;
    const float v = src[i];
    const __nv_bfloat16 h = __float2bfloat16(v);
    hi[i] = h;
    lo[i] = __float2bfloat16(v - __bfloat162float(h));
}

// ===========================================================================
// Fused pools + ad gather. grid=(B,4); y in {0,1,2}=attn pool, y==3=ad gather.
// Attn pool: 8 lanes ("oct") per history item -> 4 independent online-softmax
// chains per warp. HANG FIX vs earlier attempts:
//   (a) loop trip count is uniform across the warp (L padded to multiple of
//       16; tail uses idx=PAD_IDX, a valid table row, scored -1e9), and
//   (b) shuffles use the oct-local mask (offsets 1/2/4 never leave the oct).
// ===========================================================================
__global__ __launch_bounds__(128) void gather_pool_kernel(
    const int* __restrict__ feat,
    const int* __restrict__ h_item,
    const int* __restrict__ h_auth,
    const int* __restrict__ h_mus,
    const float* __restrict__ table,
    float* __restrict__ xout)
{
    const int row = blockIdx.x;
    const int t   = threadIdx.x;

    if (blockIdx.y == 3) {   // ad embedding gather: 8 feats * 64 floats
        const int f = t >> 4, c = t & 15;
        const int idx = feat[row * N_FEAT + f];
        const float4 v = *(const float4*)&table[(size_t)idx * K_EMB + c * 4];
        *(float4*)&xout[(size_t)row * D_IN + 3 * K_EMB + f * K_EMB + c * 4] = v;
        return;
    }

    const int* hist; int L, ad_col, off;
    if (blockIdx.y == 0)      { hist = h_item; L = 350; ad_col = 2; off = 0;   }
    else if (blockIdx.y == 1) { hist = h_auth; L = 250; ad_col = 3; off = 64;  }
    else                      { hist = h_mus;  L = 100; ad_col = 6; off = 128; }

    const int warp  = t >> 5, lane = t & 31;
    const int oct   = lane >> 3, sub = lane & 7;      // 4 octs/warp, 8 lanes/oct
    const int g_oct = warp * 4 + oct;                 // 0..15
    const unsigned omask = 0xFFu << (oct * 8);        // oct-local shuffle mask
    const int L_pad = (L + 15) & ~15;                 // uniform trip count

    __shared__ float s_ad[K_EMB];
    __shared__ float s_m[16], s_s[16];
    __shared__ float s_acc[16][K_EMB];

    const int ad_idx = feat[row * N_FEAT + ad_col];
    if (t < K_EMB) s_ad[t] = table[(size_t)ad_idx * K_EMB + t];
    __syncthreads();

    // lane owns embedding components [sub*8, sub*8+8)
    const float4 ad_a = *(const float4*)&s_ad[sub * 8];
    const float4 ad_b = *(const float4*)&s_ad[sub * 8 + 4];

    float  m = -INFINITY, s = 0.f;
    float4 acc_a = make_float4(0.f,0.f,0.f,0.f);
    float4 acc_b = make_float4(0.f,0.f,0.f,0.f);

    for (int l = g_oct; l < L_pad; l += 16) {
        // tail (l >= L) behaves exactly like padding: PAD row is valid memory
        const int idx = (l < L) ? hist[row * L + l] : PAD_IDX;
        const float* e = &table[(size_t)idx * K_EMB + sub * 8];
        const float4 ea = *(const float4*)e;
        const float4 eb = *(const float4*)(e + 4);
        float d = ea.x*ad_a.x + ea.y*ad_a.y + ea.z*ad_a.z + ea.w*ad_a.w
                + eb.x*ad_b.x + eb.y*ad_b.y + eb.z*ad_b.z + eb.w*ad_b.w;
        d += __shfl_xor_sync(omask, d, 1);
        d += __shfl_xor_sync(omask, d, 2);
        d += __shfl_xor_sync(omask, d, 4);
        if (idx == PAD_IDX) d = -1e9f;     // reference NEG_INF semantics
        const float nm = fmaxf(m, d);
        const float sc = __expf(m - nm);   // first iter: m=-inf -> 0
        const float p  = __expf(d - nm);
        s = s * sc + p;
        acc_a.x = acc_a.x*sc + p*ea.x;  acc_a.y = acc_a.y*sc + p*ea.y;
        acc_a.z = acc_a.z*sc + p*ea.z;  acc_a.w = acc_a.w*sc + p*ea.w;
        acc_b.x = acc_b.x*sc + p*eb.x;  acc_b.y = acc_b.y*sc + p*eb.y;
        acc_b.z = acc_b.z*sc + p*eb.z;  acc_b.w = acc_b.w*sc + p*eb.w;
        m = nm;
    }

    if (sub == 0) { s_m[g_oct] = m; s_s[g_oct] = s; }
    *(float4*)&s_acc[g_oct][sub * 8]     = acc_a;
    *(float4*)&s_acc[g_oct][sub * 8 + 4] = acc_b;
    __syncthreads();

    if (t < K_EMB) {
        float M = s_m[0];
        #pragma unroll
        for (int o = 1; o < 16; o++) M = fmaxf(M, s_m[o]);
        float S = 0.f, num = 0.f;
        #pragma unroll
        for (int o = 0; o < 16; o++) {
            const float sc = __expf(s_m[o] - M);
            S   += s_s[o] * sc;
            num += s_acc[o][t] * sc;
        }
        xout[(size_t)row * D_IN + off + t] = num / S;
    }
}

// ---------------------------------------------------------------------------
// Tensor-core GEMM + bias + ReLU via WMMA bf16 (bf16x3 split, fp32 accum).
// A is fp32 (split on the fly); W arrives pre-split as bf16 hi/lo.
// Block tile 128x64, BK=32, 256 threads = 8 warps (4m x 2n), 32x32 per warp.
// (Unchanged from the R10-passing kernel except W loads bf16 directly.)
// ---------------------------------------------------------------------------
#define BM   128
#define BN   64
#define BK   32
#define APAD 8
#define BPAD 8

__global__ __launch_bounds__(256) void gemm_bias_act(
    const float* __restrict__ A,
    const __nv_bfloat16* __restrict__ Wh, const __nv_bfloat16* __restrict__ Wl,
    const float* __restrict__ bias, float* __restrict__ C,
    int M, int N, int K, int relu)
{
    __shared__ __nv_bfloat16 Ah[BM][BK + APAD];
    __shared__ __nv_bfloat16 Al[BM][BK + APAD];
    __shared__ __nv_bfloat16 Bh[BK][BN + BPAD];
    __shared__ __nv_bfloat16 Bl[BK][BN + BPAD];
    __shared__ float bias_s[16][BN + 4];

    const int tid  = threadIdx.x;
    const int warp = tid >> 5;
    const int wm   = warp & 3;
    const int wn   = warp >> 2;
    const int bm   = blockIdx.y * BM;
    const int bn   = blockIdx.x * BN;

    for (int i = tid; i < 16 * BN; i += 256) {
        const int r = i >> 6, c = i & 63;
        bias_s[r][c] = bias[bn + c];
    }
    __syncthreads();

    wmma::fragment<wmma::accumulator, 16, 16, 16, float> acc[2][2];
    #pragma unroll
    for (int mi = 0; mi < 2; mi++)
        #pragma unroll
        for (int ni = 0; ni < 2; ni++)
            wmma::load_matrix_sync(acc[mi][ni], &bias_s[0][wn * 32 + ni * 16],
                                   BN + 4, wmma::mem_row_major);

    const int arow = tid >> 1, ac0 = (tid & 1) * 16;
    const int brow = tid >> 3, bc0 = (tid & 7) * 8;

    for (int k0 = 0; k0 < K; k0 += BK) {
        #pragma unroll
        for (int i = 0; i < 4; i++) {
            const float4 v = *(const float4*)&A[(size_t)(bm + arow) * K + k0 + ac0 + i * 4];
            const float f[4] = {v.x, v.y, v.z, v.w};
            __nv_bfloat16 hi[4], lo[4];
            #pragma unroll
            for (int j = 0; j < 4; j++) {
                hi[j] = __float2bfloat16(f[j]);
                lo[j] = __float2bfloat16(f[j] - __bfloat162float(hi[j]));
            }
            *(uint2*)&Ah[arow][ac0 + i * 4] = *(uint2*)hi;
            *(uint2*)&Al[arow][ac0 + i * 4] = *(uint2*)lo;
        }
        {
            const size_t wo = (size_t)(k0 + brow) * N + bn + bc0;
            *(uint4*)&Bh[brow][bc0] = *(const uint4*)&Wh[wo];
            *(uint4*)&Bl[brow][bc0] = *(const uint4*)&Wl[wo];
        }
        __syncthreads();

        #pragma unroll
        for (int kk = 0; kk < BK; kk += 16) {
            wmma::fragment<wmma::matrix_a, 16, 16, 16, __nv_bfloat16, wmma::row_major> a_h[2], a_l[2];
            wmma::fragment<wmma::matrix_b, 16, 16, 16, __nv_bfloat16, wmma::row_major> b_h[2], b_l[2];
            #pragma unroll
            for (int mi = 0; mi < 2; mi++) {
                wmma::load_matrix_sync(a_h[mi], &Ah[wm * 32 + mi * 16][kk], BK + APAD);
                wmma::load_matrix_sync(a_l[mi], &Al[wm * 32 + mi * 16][kk], BK + APAD);
            }
            #pragma unroll
            for (int ni = 0; ni < 2; ni++) {
                wmma::load_matrix_sync(b_h[ni], &Bh[kk][wn * 32 + ni * 16], BN + BPAD);
                wmma::load_matrix_sync(b_l[ni], &Bl[kk][wn * 32 + ni * 16], BN + BPAD);
            }
            #pragma unroll
            for (int mi = 0; mi < 2; mi++)
                #pragma unroll
                for (int ni = 0; ni < 2; ni++) {
                    wmma::mma_sync(acc[mi][ni], a_h[mi], b_h[ni], acc[mi][ni]);
                    wmma::mma_sync(acc[mi][ni], a_h[mi], b_l[ni], acc[mi][ni]);
                    wmma::mma_sync(acc[mi][ni], a_l[mi], b_h[ni], acc[mi][ni]);
                }
        }
        __syncthreads();
    }

    #pragma unroll
    for (int mi = 0; mi < 2; mi++)
        #pragma unroll
        for (int ni = 0; ni < 2; ni++) {
            if (relu) {
                #pragma unroll
                for (int e = 0; e < acc[mi][ni].num_elements; e++)
                    acc[mi][ni].x[e] = fmaxf(acc[mi][ni].x[e], 0.f);
            }
            wmma::store_matrix_sync(
                &C[(size_t)(bm + wm * 32 + mi * 16) * N + bn + wn * 32 + ni * 16],
                acc[mi][ni], N, wmma::mem_row_major);
        }
}

// ---------------------------------------------------------------------------
// Final: logits[row] = h3[row,:128] . Wo + bo. One warp per row.
// ---------------------------------------------------------------------------
__global__ __launch_bounds__(128) void final_dot_kernel(
    const float* __restrict__ h3, const float* __restrict__ Wo,
    const float* __restrict__ bo, float* __restrict__ out)
{
    const int lane = threadIdx.x & 31;
    const int warp = threadIdx.x >> 5;
    const int row  = blockIdx.x * 4 + warp;
    float sum = 0.f;
    #pragma unroll
    for (int i = lane; i < H3; i += 32)
        sum += h3[(size_t)row * H3 + i] * Wo[i];
    #pragma unroll
    for (int o = 16; o; o >>= 1) sum += __shfl_xor_sync(0xffffffffu, sum, o);
    if (lane == 0) out[row] = sum + bo[0];
}

// ---------------------------------------------------------------------------
extern "C" void kernel_launch(void* const* d_in, const int* in_sizes, int n_in,
                              void* d_out, int out_size)
{
    const int*   feat   = (const int*)  d_in[0];
    const int*   h_item = (const int*)  d_in[1];
    const int*   h_auth = (const int*)  d_in[2];
    const int*   h_mus  = (const int*)  d_in[3];
    const float* table  = (const float*)d_in[4];
    const float* W1 = (const float*)d_in[5];
    const float* b1 = (const float*)d_in[6];
    const float* W2 = (const float*)d_in[7];
    const float* b2 = (const float*)d_in[8];
    const float* W3 = (const float*)d_in[9];
    const float* b3 = (const float*)d_in[10];
    const float* Wo = (const float*)d_in[11];
    const float* bo = (const float*)d_in[12];
    float* out = (float*)d_out;

    float* x  = nullptr; cudaGetSymbolAddress((void**)&x,  g_x);
    float* h1 = nullptr; cudaGetSymbolAddress((void**)&h1, g_h1);
    float* h2 = nullptr; cudaGetSymbolAddress((void**)&h2, g_h2);
    float* h3 = nullptr; cudaGetSymbolAddress((void**)&h3, g_h3);
    __nv_bfloat16 *w1h, *w1l, *w2h, *w2l, *w3h, *w3l;
    cudaGetSymbolAddress((void**)&w1h, g_w1h); cudaGetSymbolAddress((void**)&w1l, g_w1l);
    cudaGetSymbolAddress((void**)&w2h, g_w2h); cudaGetSymbolAddress((void**)&w2l, g_w2l);
    cudaGetSymbolAddress((void**)&w3h, g_w3h); cudaGetSymbolAddress((void**)&w3l, g_w3l);

    // Pre-split weights to bf16 hi/lo
    split_kernel<<<(D_IN * H1 + 255) / 256, 256>>>(W1, w1h, w1l, D_IN * H1);
    split_kernel<<<(H1 * H2 + 255) / 256, 256>>>(W2, w2h, w2l, H1 * H2);
    split_kernel<<<(H2 * H3 + 255) / 256, 256>>>(W3, w3h, w3l, H2 * H3);

    // Fused pools + ad gather
    gather_pool_kernel<<<dim3(B_SZ, 4), 128>>>(feat, h_item, h_auth, h_mus, table, x);

    // MLP on tensor cores (bf16x3)
    gemm_bias_act<<<dim3(H1 / BN, B_SZ / BM), 256>>>(x,  w1h, w1l, b1, h1, B_SZ, H1, D_IN, 1);
    gemm_bias_act<<<dim3(H2 / BN, B_SZ / BM), 256>>>(h1, w2h, w2l, b2, h2, B_SZ, H2, H1, 1);
    gemm_bias_act<<<dim3(H3 / BN, B_SZ / BM), 256>>>(h2, w3h, w3l, b3, h3, B_SZ, H3, H2, 1);

    final_dot_kernel<<<B_SZ / 4, 128>>>(h3, Wo, bo, out);
}